// round 2
// baseline (speedup 1.0000x reference)
#include <cuda_runtime.h>
#include <cstdint>
#include <cstddef>

#define BB 16
#define NN 2048
#define DD 64
#define SCALE 0.022097086912079608f   // 1/sqrt(2048)
#define NEG_FILL -1000.0f

// Scratch (no allocations allowed): scores matrix + per-column softmax stats
__device__ float g_scores[(size_t)BB * NN * NN];   // [b][n][m], m contiguous
__device__ float g_cmax[BB * NN];
__device__ float g_crcp[BB * NN];

__device__ __forceinline__ void fma2(unsigned long long& d,
                                     unsigned long long a,
                                     unsigned long long b) {
    asm("fma.rn.f32x2 %0, %1, %2, %0;" : "+l"(d) : "l"(a), "l"(b));
}
__device__ __forceinline__ float2 unpack2(unsigned long long v) {
    float2 r;
    asm("mov.b64 {%0, %1}, %2;" : "=f"(r.x), "=f"(r.y) : "l"(v));
    return r;
}

// ============================================================================
// Kernel 1: scores[b][n][m] = mask ? -1000 : (q[b][n]·k[b][m]) * SCALE
// Tile: 128(n) x 128(m), K=D=64 (single pass). 256 threads, 8x8 per thread,
// f32x2-packed along m. Q duplicated in smem so the FFMA2 broadcast operand
// loads as {q,q} pairs directly (no per-iteration packing instructions).
// Mask is int32 (bool promoted by the harness).
// ============================================================================
#define A_KPAD 132   // K tile row pitch  (Ks[d][m])
#define A_QPAD 260   // Q dup row pitch   (Qd[d][2n])
#define A_SMEM ((64 * A_KPAD + 64 * A_QPAD) * 4)

__global__ void __launch_bounds__(256, 2)
scores_kernel(const float* __restrict__ q, const float* __restrict__ k,
              const int* __restrict__ mask) {
    extern __shared__ float sm[];
    float* Ks = sm;                 // [64][A_KPAD]
    float* Qd = sm + 64 * A_KPAD;   // [64][A_QPAD]

    const int t  = threadIdx.x;
    const int m0 = blockIdx.x * 128;
    const int n0 = blockIdx.y * 128;
    const int b  = blockIdx.z;

    const float* qg = q + ((size_t)b * NN + n0) * DD;
    const float* kg = k + ((size_t)b * NN + m0) * DD;

    // Load K tile (128 x 64), store transposed Ks[d][m]
#pragma unroll
    for (int i = 0; i < 8; i++) {
        int idx = i * 256 + t;        // float4 units
        int row = idx >> 4;           // 0..127 (m local)
        int c4  = idx & 15;
        float4 vv = *(const float4*)(kg + (size_t)row * DD + c4 * 4);
        int d0 = c4 * 4;
        Ks[(d0 + 0) * A_KPAD + row] = vv.x;
        Ks[(d0 + 1) * A_KPAD + row] = vv.y;
        Ks[(d0 + 2) * A_KPAD + row] = vv.z;
        Ks[(d0 + 3) * A_KPAD + row] = vv.w;
    }
    // Load Q tile (128 x 64), store duplicated-transposed Qd[d][2n],Qd[d][2n+1]
#pragma unroll
    for (int i = 0; i < 8; i++) {
        int idx = i * 256 + t;
        int row = idx >> 4;           // 0..127 (n local)
        int c4  = idx & 15;
        float4 vv = *(const float4*)(qg + (size_t)row * DD + c4 * 4);
        int d0 = c4 * 4;
        float* p;
        p = Qd + (d0 + 0) * A_QPAD + 2 * row; p[0] = vv.x; p[1] = vv.x;
        p = Qd + (d0 + 1) * A_QPAD + 2 * row; p[0] = vv.y; p[1] = vv.y;
        p = Qd + (d0 + 2) * A_QPAD + 2 * row; p[0] = vv.z; p[1] = vv.z;
        p = Qd + (d0 + 3) * A_QPAD + 2 * row; p[0] = vv.w; p[1] = vv.w;
    }
    __syncthreads();

    const int tx = t & 15, ty = t >> 4;
    const int mb = tx * 8, nb = ty * 8;

    unsigned long long acc[8][4];
#pragma unroll
    for (int i = 0; i < 8; i++)
#pragma unroll
        for (int j = 0; j < 4; j++) acc[i][j] = 0ULL;

#pragma unroll 4
    for (int d = 0; d < 64; d++) {
        const float* krow = Ks + d * A_KPAD + mb;
        const float* qrow = Qd + d * A_QPAD + 2 * nb;
        unsigned long long kp[4], qp[8];
        {
            ulonglong2 u0 = *(const ulonglong2*)(krow);
            ulonglong2 u1 = *(const ulonglong2*)(krow + 4);
            kp[0] = u0.x; kp[1] = u0.y; kp[2] = u1.x; kp[3] = u1.y;
        }
#pragma unroll
        for (int i = 0; i < 4; i++) {
            ulonglong2 u = *(const ulonglong2*)(qrow + 4 * i);
            qp[2 * i] = u.x; qp[2 * i + 1] = u.y;
        }
#pragma unroll
        for (int i = 0; i < 8; i++)
#pragma unroll
            for (int j = 0; j < 4; j++)
                fma2(acc[i][j], kp[j], qp[i]);
    }

    // Epilogue: scale, mask (int32 nonzero => masked), store
#pragma unroll
    for (int i = 0; i < 8; i++) {
        int n = n0 + nb + i;
        size_t base = ((size_t)b * NN + n) * NN + (m0 + mb);
        int4 ma = *(const int4*)(mask + base);
        int4 mb4 = *(const int4*)(mask + base + 4);
        float vals[8];
#pragma unroll
        for (int j = 0; j < 4; j++) {
            float2 p = unpack2(acc[i][j]);
            vals[2 * j]     = p.x * SCALE;
            vals[2 * j + 1] = p.y * SCALE;
        }
        if (ma.x)  vals[0] = NEG_FILL;
        if (ma.y)  vals[1] = NEG_FILL;
        if (ma.z)  vals[2] = NEG_FILL;
        if (ma.w)  vals[3] = NEG_FILL;
        if (mb4.x) vals[4] = NEG_FILL;
        if (mb4.y) vals[5] = NEG_FILL;
        if (mb4.z) vals[6] = NEG_FILL;
        if (mb4.w) vals[7] = NEG_FILL;
        float4 o0 = make_float4(vals[0], vals[1], vals[2], vals[3]);
        float4 o1 = make_float4(vals[4], vals[5], vals[6], vals[7]);
        *(float4*)(g_scores + base)     = o0;
        *(float4*)(g_scores + base + 4) = o1;
    }
}

// ============================================================================
// Kernel 2: per-column (fixed b,m) online max / sum-exp over n
// ============================================================================
__global__ void colstats_kernel() {
    const int m = blockIdx.x * 256 + threadIdx.x;
    const int b = blockIdx.y;
    const float* col = g_scores + (size_t)b * NN * NN + m;
    float mx = -3.402823466e38f, sum = 0.f;
    for (int n = 0; n < NN; n += 4) {
        float s0 = col[(size_t)(n + 0) * NN];
        float s1 = col[(size_t)(n + 1) * NN];
        float s2 = col[(size_t)(n + 2) * NN];
        float s3 = col[(size_t)(n + 3) * NN];
        float s[4] = {s0, s1, s2, s3};
#pragma unroll
        for (int u = 0; u < 4; u++) {
            float nm = fmaxf(mx, s[u]);
            sum = sum * __expf(mx - nm) + __expf(s[u] - nm);
            mx = nm;
        }
    }
    g_cmax[b * NN + m] = mx;
    g_crcp[b * NN + m] = 1.f / sum;
}

// ============================================================================
// Kernel 3: out[b][n][d] = sum_m exp(s-max_m)*rcp_m * v[b][m][d]
// Tile: 64(n) x 64(d=full), K-chunks of 32 m. P duplicated in smem for f32x2
// along d. 256 threads, 4x4 per thread (f32x2 pairs along d).
// ============================================================================
#define C_VPAD 68
#define C_PPAD 132

__global__ void __launch_bounds__(256)
out_kernel(const float* __restrict__ v, float* __restrict__ out) {
    __shared__ __align__(16) float Vs[32 * C_VPAD];
    __shared__ __align__(16) float Pd[32 * C_PPAD];
    __shared__ float scm[32], scr[32];

    const int t  = threadIdx.x;
    const int n0 = blockIdx.x * 64;
    const int b  = blockIdx.y;
    const int tx = t & 15, ty = t >> 4;

    unsigned long long acc[4][2];
#pragma unroll
    for (int i = 0; i < 4; i++) { acc[i][0] = 0ULL; acc[i][1] = 0ULL; }

    for (int ck = 0; ck < NN / 32; ck++) {
        const int mm0 = ck * 32;
        __syncthreads();                       // previous compute done
        if (t < 32) {
            scm[t] = g_cmax[b * NN + mm0 + t];
            scr[t] = g_crcp[b * NN + mm0 + t];
        }
        __syncthreads();                       // stats visible

        // P tile: 64(n) x 32(m) -> Pd[m][2n] duplicated, exp applied on the fly
        const float* sg = g_scores + ((size_t)b * NN + n0) * NN + mm0;
#pragma unroll
        for (int i = 0; i < 2; i++) {
            int idx = i * 256 + t;             // float4 units, 8 per row
            int row = idx >> 3;                // n local 0..63
            int c4  = idx & 7;
            float4 s4 = *(const float4*)(sg + (size_t)row * NN + c4 * 4);
            int ml = c4 * 4;
            float p0 = __expf(s4.x - scm[ml + 0]) * scr[ml + 0];
            float p1 = __expf(s4.y - scm[ml + 1]) * scr[ml + 1];
            float p2 = __expf(s4.z - scm[ml + 2]) * scr[ml + 2];
            float p3 = __expf(s4.w - scm[ml + 3]) * scr[ml + 3];
            float* p;
            p = Pd + (ml + 0) * C_PPAD + 2 * row; p[0] = p0; p[1] = p0;
            p = Pd + (ml + 1) * C_PPAD + 2 * row; p[0] = p1; p[1] = p1;
            p = Pd + (ml + 2) * C_PPAD + 2 * row; p[0] = p2; p[1] = p2;
            p = Pd + (ml + 3) * C_PPAD + 2 * row; p[0] = p3; p[1] = p3;
        }
        // V tile: 32(m) x 64(d)
        const float* vg = v + ((size_t)b * NN + mm0) * DD;
#pragma unroll
        for (int i = 0; i < 2; i++) {
            int idx = i * 256 + t;
            int row = idx >> 4;                // m local 0..31
            int c4  = idx & 15;
            float4 vv = *(const float4*)(vg + (size_t)row * DD + c4 * 4);
            *(float4*)(Vs + row * C_VPAD + c4 * 4) = vv;
        }
        __syncthreads();                       // tiles visible

#pragma unroll
        for (int kk = 0; kk < 32; kk++) {
            const float* prow = Pd + kk * C_PPAD + 2 * (ty * 4);
            const float* vrow = Vs + kk * C_VPAD + tx * 4;
            ulonglong2 pa = *(const ulonglong2*)(prow);
            ulonglong2 pb = *(const ulonglong2*)(prow + 4);
            ulonglong2 va = *(const ulonglong2*)(vrow);
            unsigned long long pp[4] = {pa.x, pa.y, pb.x, pb.y};
            unsigned long long vp[2] = {va.x, va.y};
#pragma unroll
            for (int i = 0; i < 4; i++)
#pragma unroll
                for (int j = 0; j < 2; j++)
                    fma2(acc[i][j], vp[j], pp[i]);
        }
    }

#pragma unroll
    for (int i = 0; i < 4; i++) {
        int n = n0 + ty * 4 + i;
        float2 a0 = unpack2(acc[i][0]);
        float2 a1 = unpack2(acc[i][1]);
        float4 o = make_float4(a0.x, a0.y, a1.x, a1.y);
        *(float4*)(out + ((size_t)b * NN + n) * DD + tx * 4) = o;
    }
}

// ============================================================================
extern "C" void kernel_launch(void* const* d_in, const int* in_sizes, int n_in,
                              void* d_out, int out_size) {
    const float* q = (const float*)d_in[0];
    const float* k = (const float*)d_in[1];
    const float* v = (const float*)d_in[2];
    const int* mask = (const int*)d_in[3];
    float* out = (float*)d_out;

    cudaFuncSetAttribute(scores_kernel,
                         cudaFuncAttributeMaxDynamicSharedMemorySize, A_SMEM);

    scores_kernel<<<dim3(NN / 128, NN / 128, BB), 256, A_SMEM>>>(q, k, mask);
    colstats_kernel<<<dim3(NN / 256, BB), 256>>>();
    out_kernel<<<dim3(NN / 64, BB), 256>>>(v, out);
}

// round 6
// speedup vs baseline: 1.6774x; 1.6774x over previous
#include <cuda_runtime.h>
#include <cuda_bf16.h>
#include <cstdint>
#include <cstddef>

#define BB 16
#define NN 2048
#define DD 64
#define SCALE 0.022097086912079608f   // 1/sqrt(2048)
#define NEG_FILL -1000.0f

// ---------------------------------------------------------------------------
// Scratch (no allocations allowed)
// ---------------------------------------------------------------------------
__device__ float g_scores[(size_t)BB * NN * NN];   // [b][n][m], m contiguous
__device__ float g_cmax[BB * NN];
__device__ float g_crcp[BB * NN];
__device__ __align__(16) __nv_bfloat16 g_qh[(size_t)BB * NN * DD];
__device__ __align__(16) __nv_bfloat16 g_ql[(size_t)BB * NN * DD];
__device__ __align__(16) __nv_bfloat16 g_kh[(size_t)BB * NN * DD];
__device__ __align__(16) __nv_bfloat16 g_kl[(size_t)BB * NN * DD];

// ---------------------------------------------------------------------------
// Helpers
// ---------------------------------------------------------------------------
__device__ __forceinline__ uint32_t smem_u32(const void* p) {
    uint32_t a;
    asm("{ .reg .u64 t; cvta.to.shared.u64 t, %1; cvt.u32.u64 %0, t; }"
        : "=r"(a) : "l"(p));
    return a;
}

#define LDSM4(r, a)                                                            \
    asm volatile("ldmatrix.sync.aligned.m8n8.x4.shared.b16 {%0,%1,%2,%3}, [%4];" \
        : "=r"((r)[0]), "=r"((r)[1]), "=r"((r)[2]), "=r"((r)[3]) : "r"(a))
#define LDSM4T(r, a)                                                           \
    asm volatile("ldmatrix.sync.aligned.m8n8.x4.trans.shared.b16 {%0,%1,%2,%3}, [%4];" \
        : "=r"((r)[0]), "=r"((r)[1]), "=r"((r)[2]), "=r"((r)[3]) : "r"(a))
#define MMA_BF16(c, a, b)                                                      \
    asm volatile("mma.sync.aligned.m16n8k16.row.col.f32.bf16.bf16.f32 "        \
        "{%0,%1,%2,%3}, {%4,%5,%6,%7}, {%8,%9}, {%0,%1,%2,%3};"                \
        : "+f"((c)[0]), "+f"((c)[1]), "+f"((c)[2]), "+f"((c)[3])               \
        : "r"((a)[0]), "r"((a)[1]), "r"((a)[2]), "r"((a)[3]),                  \
          "r"((b)[0]), "r"((b)[1]))

__device__ __forceinline__ void split2(float x, float y, uint32_t& hi, uint32_t& lo) {
    __nv_bfloat16 hx = __float2bfloat16(x), hy = __float2bfloat16(y);
    __nv_bfloat16 lx = __float2bfloat16(x - __bfloat162float(hx));
    __nv_bfloat16 ly = __float2bfloat16(y - __bfloat162float(hy));
    hi = (uint32_t)__bfloat16_as_ushort(hx) | ((uint32_t)__bfloat16_as_ushort(hy) << 16);
    lo = (uint32_t)__bfloat16_as_ushort(lx) | ((uint32_t)__bfloat16_as_ushort(ly) << 16);
}

// ============================================================================
// Kernel 0: split q, k into bf16 hi/lo
// ============================================================================
__global__ void prep_kernel(const float* __restrict__ q,
                            const float* __restrict__ k) {
    int i = blockIdx.x * 256 + threadIdx.x;     // float4 index, 524288 total
    float4 vq = ((const float4*)q)[i];
    float4 vk = ((const float4*)k)[i];
    uint32_t h0, h1, l0, l1;
    split2(vq.x, vq.y, h0, l0); split2(vq.z, vq.w, h1, l1);
    ((uint2*)g_qh)[i] = make_uint2(h0, h1);
    ((uint2*)g_ql)[i] = make_uint2(l0, l1);
    split2(vk.x, vk.y, h0, l0); split2(vk.z, vk.w, h1, l1);
    ((uint2*)g_kh)[i] = make_uint2(h0, h1);
    ((uint2*)g_kl)[i] = make_uint2(l0, l1);
}

// ============================================================================
// Kernel 1: scores via HMMA (mma.sync bf16, hi/lo 3-pass split).
// Block 128(n) x 128(m); 8 warps in 2(n) x 4(m); warp tile 64x32.
// smem tiles [row][64 bf16] = 128B rows, 16B-block XOR swizzle.
// ============================================================================
#define SC_SMEM 65536

__global__ void __launch_bounds__(256)
scores_mma_kernel(const int* __restrict__ mask) {
    extern __shared__ char smc[];
    const uint32_t sb = smem_u32(smc);
    const int t = threadIdx.x, l = t & 31, wid = t >> 5;
    const int m0 = blockIdx.x * 128, n0 = blockIdx.y * 128, b = blockIdx.z;
    const int wn = wid >> 2, wm = wid & 3;

    const uint32_t QH = 0, QL = 16384, KH = 32768, KL = 49152;

    // Load tiles (each 128 rows x 128B), swizzled
    {
        const uint4* qh = (const uint4*)(g_qh + ((size_t)b * NN + n0) * DD);
        const uint4* ql = (const uint4*)(g_ql + ((size_t)b * NN + n0) * DD);
        const uint4* kh = (const uint4*)(g_kh + ((size_t)b * NN + m0) * DD);
        const uint4* kl = (const uint4*)(g_kl + ((size_t)b * NN + m0) * DD);
#pragma unroll
        for (int i = 0; i < 4; i++) {
            int idx = i * 256 + t;
            int row = idx >> 3, q = idx & 7;
            uint32_t off = (uint32_t)(row * 128 + ((q ^ (row & 7)) << 4));
            *(uint4*)(smc + QH + off) = qh[idx];
            *(uint4*)(smc + QL + off) = ql[idx];
            *(uint4*)(smc + KH + off) = kh[idx];
            *(uint4*)(smc + KL + off) = kl[idx];
        }
    }
    __syncthreads();

    float c[4][4][4];
#pragma unroll
    for (int i = 0; i < 4; i++)
#pragma unroll
        for (int j = 0; j < 4; j++)
#pragma unroll
            for (int r = 0; r < 4; r++) c[i][j][r] = 0.f;

#pragma unroll
    for (int pass = 0; pass < 3; pass++) {
        const uint32_t Ab = sb + ((pass == 2) ? QL : QH);
        const uint32_t Bb = sb + ((pass == 1) ? KL : KH);
#pragma unroll
        for (int ks = 0; ks < 4; ks++) {
            uint32_t a[4][4], bf[2][4];
#pragma unroll
            for (int fn = 0; fn < 4; fn++) {
                int row = wn * 64 + fn * 16 + (l & 15);
                int blk = ks * 2 + (l >> 4);
                LDSM4(a[fn], Ab + row * 128 + ((blk ^ (row & 7)) << 4));
            }
#pragma unroll
            for (int p = 0; p < 2; p++) {
                int row = wm * 32 + p * 16 + ((l >> 4) << 3) + (l & 7);
                int blk = ks * 2 + ((l >> 3) & 1);
                LDSM4(bf[p], Bb + row * 128 + ((blk ^ (row & 7)) << 4));
            }
#pragma unroll
            for (int fn = 0; fn < 4; fn++)
#pragma unroll
                for (int fm = 0; fm < 4; fm++)
                    MMA_BF16(c[fn][fm], a[fn], &bf[fm >> 1][(fm & 1) * 2]);
        }
    }

    // Epilogue: scale + mask + store
    const int g = l >> 2, tig = l & 3;
#pragma unroll
    for (int fn = 0; fn < 4; fn++) {
#pragma unroll
        for (int h = 0; h < 2; h++) {
            int n = n0 + wn * 64 + fn * 16 + g + h * 8;
#pragma unroll
            for (int fm = 0; fm < 4; fm++) {
                int m = m0 + wm * 32 + fm * 8 + tig * 2;
                size_t addr = ((size_t)b * NN + n) * NN + m;
                int2 mk = *(const int2*)(mask + addr);
                float2 o;
                o.x = mk.x ? NEG_FILL : c[fn][fm][h * 2] * SCALE;
                o.y = mk.y ? NEG_FILL : c[fn][fm][h * 2 + 1] * SCALE;
                *(float2*)(g_scores + addr) = o;
            }
        }
    }
}

// ============================================================================
// Kernel 2: per-column (fixed b,m) online max / sum-exp over n
// ============================================================================
__global__ void colstats_kernel() {
    const int m = blockIdx.x * 256 + threadIdx.x;
    const int b = blockIdx.y;
    const float* col = g_scores + (size_t)b * NN * NN + m;
    float mx = -3.402823466e38f, sum = 0.f;
    for (int n = 0; n < NN; n += 4) {
        float s[4];
        s[0] = col[(size_t)(n + 0) * NN];
        s[1] = col[(size_t)(n + 1) * NN];
        s[2] = col[(size_t)(n + 2) * NN];
        s[3] = col[(size_t)(n + 3) * NN];
#pragma unroll
        for (int u = 0; u < 4; u++) {
            float nm = fmaxf(mx, s[u]);
            sum = sum * __expf(mx - nm) + __expf(s[u] - nm);
            mx = nm;
        }
    }
    g_cmax[b * NN + m] = mx;
    g_crcp[b * NN + m] = 1.f / sum;
}

// ============================================================================
// Kernel 3: out = P·V via HMMA. Block 128(n) x 64(d); k-chunks of 64 m.
// P staged with exp+split hi/lo; V loaded natural [m][d], B frags via
// ldmatrix.trans. 8 warps in 4(n) x 2(d); warp tile 32x32.
// ============================================================================
#define O_PH 0
#define O_PL 16384
#define O_VH 32768
#define O_VL 40960
#define O_CM 49152
#define O_CR 49408
#define O_SMEM 49664

__global__ void __launch_bounds__(256)
out_mma_kernel(const float* __restrict__ v, float* __restrict__ out) {
    extern __shared__ char smc[];
    const uint32_t sb = smem_u32(smc);
    float* scm = (float*)(smc + O_CM);
    float* scr = (float*)(smc + O_CR);
    const int t = threadIdx.x, l = t & 31, wid = t >> 5;
    const int nblk = blockIdx.x * 128, b = blockIdx.y;
    const int wn = wid >> 1, wd = wid & 1;

    float c[2][4][4];
#pragma unroll
    for (int i = 0; i < 2; i++)
#pragma unroll
        for (int j = 0; j < 4; j++)
#pragma unroll
            for (int r = 0; r < 4; r++) c[i][j][r] = 0.f;

    for (int ck = 0; ck < NN / 64; ck++) {
        const int m0c = ck * 64;
        __syncthreads();
        if (t < 64) {
            scm[t] = g_cmax[b * NN + m0c + t];
            scr[t] = g_crcp[b * NN + m0c + t];
        }
        __syncthreads();

        // Stage P (128n x 64m): exp + hi/lo split, swizzled
        const float* sg = g_scores + ((size_t)b * NN + nblk) * NN + m0c;
#pragma unroll
        for (int i = 0; i < 8; i++) {
            int idx = i * 256 + t;
            int row = idx >> 4, c4 = idx & 15;
            float4 s4 = *(const float4*)(sg + (size_t)row * NN + c4 * 4);
            int ml = c4 * 4;
            float p0 = __expf(s4.x - scm[ml + 0]) * scr[ml + 0];
            float p1 = __expf(s4.y - scm[ml + 1]) * scr[ml + 1];
            float p2 = __expf(s4.z - scm[ml + 2]) * scr[ml + 2];
            float p3 = __expf(s4.w - scm[ml + 3]) * scr[ml + 3];
            uint32_t h01, l01, h23, l23;
            split2(p0, p1, h01, l01);
            split2(p2, p3, h23, l23);
            uint32_t off = (uint32_t)(row * 128 + (((c4 >> 1) ^ (row & 7)) << 4) +
                                      ((c4 & 1) << 3));
            *(uint2*)(smc + O_PH + off) = make_uint2(h01, h23);
            *(uint2*)(smc + O_PL + off) = make_uint2(l01, l23);
        }
        // Stage V (64m x 64d): hi/lo split, swizzled
        const float* vg = v + ((size_t)b * NN + m0c) * DD;
#pragma unroll
        for (int i = 0; i < 4; i++) {
            int idx = i * 256 + t;
            int row = idx >> 4, c4 = idx & 15;
            float4 v4 = *(const float4*)(vg + (size_t)row * DD + c4 * 4);
            uint32_t h01, l01, h23, l23;
            split2(v4.x, v4.y, h01, l01);
            split2(v4.z, v4.w, h23, l23);
            uint32_t off = (uint32_t)(row * 128 + (((c4 >> 1) ^ (row & 7)) << 4) +
                                      ((c4 & 1) << 3));
            *(uint2*)(smc + O_VH + off) = make_uint2(h01, h23);
            *(uint2*)(smc + O_VL + off) = make_uint2(l01, l23);
        }
        __syncthreads();

#pragma unroll
        for (int pass = 0; pass < 3; pass++) {
            const uint32_t Ab = sb + ((pass == 2) ? O_PL : O_PH);
            const uint32_t Bb = sb + ((pass == 1) ? O_VL : O_VH);
#pragma unroll
            for (int ks = 0; ks < 4; ks++) {
                uint32_t a[2][4], bf[2][4];
#pragma unroll
                for (int fn = 0; fn < 2; fn++) {
                    int row = wn * 32 + fn * 16 + (l & 15);
                    int blk = ks * 2 + (l >> 4);
                    LDSM4(a[fn], Ab + row * 128 + ((blk ^ (row & 7)) << 4));
                }
#pragma unroll
                for (int p = 0; p < 2; p++) {
                    int row = ks * 16 + ((l >> 3) & 1) * 8 + (l & 7);
                    int blk = wd * 4 + p * 2 + (l >> 4);
                    LDSM4T(bf[p], Bb + row * 128 + ((blk ^ (row & 7)) << 4));
                }
#pragma unroll
                for (int fn = 0; fn < 2; fn++)
#pragma unroll
                    for (int fb = 0; fb < 4; fb++)
                        MMA_BF16(c[fn][fb], a[fn], &bf[fb >> 1][(fb & 1) * 2]);
            }
        }
    }

    const int g = l >> 2, tig = l & 3;
#pragma unroll
    for (int fn = 0; fn < 2; fn++) {
#pragma unroll
        for (int h = 0; h < 2; h++) {
            int n = nblk + wn * 32 + fn * 16 + g + h * 8;
#pragma unroll
            for (int fb = 0; fb < 4; fb++) {
                int d = wd * 32 + fb * 8 + tig * 2;
                float2 o = make_float2(c[fn][fb][h * 2], c[fn][fb][h * 2 + 1]);
                *(float2*)(out + ((size_t)b * NN + n) * DD + d) = o;
            }
        }
    }
}

// ============================================================================
extern "C" void kernel_launch(void* const* d_in, const int* in_sizes, int n_in,
                              void* d_out, int out_size) {
    const float* q = (const float*)d_in[0];
    const float* k = (const float*)d_in[1];
    const float* v = (const float*)d_in[2];
    const int* mask = (const int*)d_in[3];
    float* out = (float*)d_out;

    cudaFuncSetAttribute(scores_mma_kernel,
                         cudaFuncAttributeMaxDynamicSharedMemorySize, SC_SMEM);
    cudaFuncSetAttribute(out_mma_kernel,
                         cudaFuncAttributeMaxDynamicSharedMemorySize, O_SMEM);

    prep_kernel<<<2048, 256>>>(q, k);
    scores_mma_kernel<<<dim3(NN / 128, NN / 128, BB), 256, SC_SMEM>>>(mask);
    colstats_kernel<<<dim3(NN / 256, BB), 256>>>();
    out_mma_kernel<<<dim3(NN / 128, BB), 256, O_SMEM>>>(v, out);
}

// round 7
// speedup vs baseline: 2.7864x; 1.6612x over previous
#include <cuda_runtime.h>
#include <cuda_bf16.h>
#include <cstdint>
#include <cstddef>

#define BB 16
#define NN 2048
#define DD 64
#define SCALE 0.022097086912079608f   // 1/sqrt(2048)
#define NEG_FILL -1000.0f
#define MSPLIT 4
#define NCHUNK 8

// ---------------------------------------------------------------------------
// Scratch (no allocations allowed)
// ---------------------------------------------------------------------------
__device__ float g_scores[(size_t)BB * NN * NN];   // [b][n][m], m contiguous
__device__ float g_cmax[BB * NN];
__device__ float g_crcp[BB * NN];
__device__ float g_pmx[NCHUNK * BB * NN];
__device__ float g_psum[NCHUNK * BB * NN];
__device__ float g_pout[(size_t)MSPLIT * BB * NN * DD];
__device__ __align__(16) __nv_bfloat16 g_qh[(size_t)BB * NN * DD];
__device__ __align__(16) __nv_bfloat16 g_ql[(size_t)BB * NN * DD];
__device__ __align__(16) __nv_bfloat16 g_kh[(size_t)BB * NN * DD];
__device__ __align__(16) __nv_bfloat16 g_kl[(size_t)BB * NN * DD];

// ---------------------------------------------------------------------------
// Helpers
// ---------------------------------------------------------------------------
__device__ __forceinline__ uint32_t smem_u32(const void* p) {
    uint32_t a;
    asm("{ .reg .u64 t; cvta.to.shared.u64 t, %1; cvt.u32.u64 %0, t; }"
        : "=r"(a) : "l"(p));
    return a;
}

#define LDSM4(r, a)                                                            \
    asm volatile("ldmatrix.sync.aligned.m8n8.x4.shared.b16 {%0,%1,%2,%3}, [%4];" \
        : "=r"((r)[0]), "=r"((r)[1]), "=r"((r)[2]), "=r"((r)[3]) : "r"(a))
#define LDSM4T(r, a)                                                           \
    asm volatile("ldmatrix.sync.aligned.m8n8.x4.trans.shared.b16 {%0,%1,%2,%3}, [%4];" \
        : "=r"((r)[0]), "=r"((r)[1]), "=r"((r)[2]), "=r"((r)[3]) : "r"(a))
#define MMA_BF16(c, a, b)                                                      \
    asm volatile("mma.sync.aligned.m16n8k16.row.col.f32.bf16.bf16.f32 "        \
        "{%0,%1,%2,%3}, {%4,%5,%6,%7}, {%8,%9}, {%0,%1,%2,%3};"                \
        : "+f"((c)[0]), "+f"((c)[1]), "+f"((c)[2]), "+f"((c)[3])               \
        : "r"((a)[0]), "r"((a)[1]), "r"((a)[2]), "r"((a)[3]),                  \
          "r"((b)[0]), "r"((b)[1]))

__device__ __forceinline__ void split2(float x, float y, uint32_t& hi, uint32_t& lo) {
    __nv_bfloat16 hx = __float2bfloat16(x), hy = __float2bfloat16(y);
    __nv_bfloat16 lx = __float2bfloat16(x - __bfloat162float(hx));
    __nv_bfloat16 ly = __float2bfloat16(y - __bfloat162float(hy));
    hi = (uint32_t)__bfloat16_as_ushort(hx) | ((uint32_t)__bfloat16_as_ushort(hy) << 16);
    lo = (uint32_t)__bfloat16_as_ushort(lx) | ((uint32_t)__bfloat16_as_ushort(ly) << 16);
}

// ============================================================================
// Kernel 0: split q, k into bf16 hi/lo
// ============================================================================
__global__ void prep_kernel(const float* __restrict__ q,
                            const float* __restrict__ k) {
    int i = blockIdx.x * 256 + threadIdx.x;     // float4 index, 524288 total
    float4 vq = ((const float4*)q)[i];
    float4 vk = ((const float4*)k)[i];
    uint32_t h0, h1, l0, l1;
    split2(vq.x, vq.y, h0, l0); split2(vq.z, vq.w, h1, l1);
    ((uint2*)g_qh)[i] = make_uint2(h0, h1);
    ((uint2*)g_ql)[i] = make_uint2(l0, l1);
    split2(vk.x, vk.y, h0, l0); split2(vk.z, vk.w, h1, l1);
    ((uint2*)g_kh)[i] = make_uint2(h0, h1);
    ((uint2*)g_kl)[i] = make_uint2(l0, l1);
}

// ============================================================================
// Kernel 1: scores via HMMA (mma.sync bf16, hi/lo 3-pass split).
// Block 128(n) x 128(m); 8 warps in 2(n) x 4(m); warp tile 64x32.
// ============================================================================
#define SC_SMEM 65536

__global__ void __launch_bounds__(256, 2)
scores_mma_kernel(const int* __restrict__ mask) {
    extern __shared__ char smc[];
    const uint32_t sb = smem_u32(smc);
    const int t = threadIdx.x, l = t & 31, wid = t >> 5;
    const int m0 = blockIdx.x * 128, n0 = blockIdx.y * 128, b = blockIdx.z;
    const int wn = wid >> 2, wm = wid & 3;

    const uint32_t QH = 0, QL = 16384, KH = 32768, KL = 49152;

    {
        const uint4* qh = (const uint4*)(g_qh + ((size_t)b * NN + n0) * DD);
        const uint4* ql = (const uint4*)(g_ql + ((size_t)b * NN + n0) * DD);
        const uint4* kh = (const uint4*)(g_kh + ((size_t)b * NN + m0) * DD);
        const uint4* kl = (const uint4*)(g_kl + ((size_t)b * NN + m0) * DD);
#pragma unroll
        for (int i = 0; i < 4; i++) {
            int idx = i * 256 + t;
            int row = idx >> 3, q = idx & 7;
            uint32_t off = (uint32_t)(row * 128 + ((q ^ (row & 7)) << 4));
            *(uint4*)(smc + QH + off) = qh[idx];
            *(uint4*)(smc + QL + off) = ql[idx];
            *(uint4*)(smc + KH + off) = kh[idx];
            *(uint4*)(smc + KL + off) = kl[idx];
        }
    }
    __syncthreads();

    float c[4][4][4];
#pragma unroll
    for (int i = 0; i < 4; i++)
#pragma unroll
        for (int j = 0; j < 4; j++)
#pragma unroll
            for (int r = 0; r < 4; r++) c[i][j][r] = 0.f;

#pragma unroll
    for (int pass = 0; pass < 3; pass++) {
        const uint32_t Ab = sb + ((pass == 2) ? QL : QH);
        const uint32_t Bb = sb + ((pass == 1) ? KL : KH);
#pragma unroll
        for (int ks = 0; ks < 4; ks++) {
            uint32_t a[4][4], bf[2][4];
#pragma unroll
            for (int fn = 0; fn < 4; fn++) {
                int row = wn * 64 + fn * 16 + (l & 15);
                int blk = ks * 2 + (l >> 4);
                LDSM4(a[fn], Ab + row * 128 + ((blk ^ (row & 7)) << 4));
            }
#pragma unroll
            for (int p = 0; p < 2; p++) {
                int row = wm * 32 + p * 16 + ((l >> 4) << 3) + (l & 7);
                int blk = ks * 2 + ((l >> 3) & 1);
                LDSM4(bf[p], Bb + row * 128 + ((blk ^ (row & 7)) << 4));
            }
#pragma unroll
            for (int fn = 0; fn < 4; fn++)
#pragma unroll
                for (int fm = 0; fm < 4; fm++)
                    MMA_BF16(c[fn][fm], a[fn], &bf[fm >> 1][(fm & 1) * 2]);
        }
    }

    // Epilogue: scale + mask + store
    const int g = l >> 2, tig = l & 3;
#pragma unroll
    for (int fn = 0; fn < 4; fn++) {
#pragma unroll
        for (int h = 0; h < 2; h++) {
            int n = n0 + wn * 64 + fn * 16 + g + h * 8;
#pragma unroll
            for (int fm = 0; fm < 4; fm++) {
                int m = m0 + wm * 32 + fm * 8 + tig * 2;
                size_t addr = ((size_t)b * NN + n) * NN + m;
                int2 mk = *(const int2*)(mask + addr);
                float2 o;
                o.x = mk.x ? NEG_FILL : c[fn][fm][h * 2] * SCALE;
                o.y = mk.y ? NEG_FILL : c[fn][fm][h * 2 + 1] * SCALE;
                *(float2*)(g_scores + addr) = o;
            }
        }
    }
}

// ============================================================================
// Kernel 2a: per-column partial max/sumexp over an n-chunk of 256
// grid (NN/256, NCHUNK, BB)
// ============================================================================
__global__ void colstats1_kernel() {
    const int m = blockIdx.x * 256 + threadIdx.x;
    const int nc = blockIdx.y;
    const int b = blockIdx.z;
    const float* col = g_scores + (size_t)b * NN * NN +
                       (size_t)nc * (NN / NCHUNK) * NN + m;
    float mx = -3.402823466e38f, sum = 0.f;
    for (int n = 0; n < NN / NCHUNK; n += 4) {
        float s[4];
        s[0] = col[(size_t)(n + 0) * NN];
        s[1] = col[(size_t)(n + 1) * NN];
        s[2] = col[(size_t)(n + 2) * NN];
        s[3] = col[(size_t)(n + 3) * NN];
#pragma unroll
        for (int u = 0; u < 4; u++) {
            float nm = fmaxf(mx, s[u]);
            sum = sum * __expf(mx - nm) + __expf(s[u] - nm);
            mx = nm;
        }
    }
    g_pmx[(nc * BB + b) * NN + m] = mx;
    g_psum[(nc * BB + b) * NN + m] = sum;
}

// ============================================================================
// Kernel 2b: combine NCHUNK partials -> g_cmax, g_crcp
// ============================================================================
__global__ void colstats2_kernel() {
    const int m = blockIdx.x * 256 + threadIdx.x;
    const int b = blockIdx.y;
    float lm[NCHUNK], ls[NCHUNK];
    float mx = -3.402823466e38f;
#pragma unroll
    for (int i = 0; i < NCHUNK; i++) {
        lm[i] = g_pmx[(i * BB + b) * NN + m];
        ls[i] = g_psum[(i * BB + b) * NN + m];
        mx = fmaxf(mx, lm[i]);
    }
    float S = 0.f;
#pragma unroll
    for (int i = 0; i < NCHUNK; i++) S += ls[i] * __expf(lm[i] - mx);
    g_cmax[b * NN + m] = mx;
    g_crcp[b * NN + m] = 1.f / S;
}

// ============================================================================
// Kernel 3: partial out = P·V via HMMA over an m-range of NN/MSPLIT.
// Block 128(n) x 64(d); k-chunks of 64 m. grid (NN/128, BB, MSPLIT).
// ============================================================================
#define O_PH 0
#define O_PL 16384
#define O_VH 32768
#define O_VL 40960
#define O_CM 49152
#define O_CR 49408
#define O_SMEM 49664

__global__ void __launch_bounds__(256, 2)
out_mma_kernel(const float* __restrict__ v) {
    extern __shared__ char smc[];
    const uint32_t sb = smem_u32(smc);
    float* scm = (float*)(smc + O_CM);
    float* scr = (float*)(smc + O_CR);
    const int t = threadIdx.x, l = t & 31, wid = t >> 5;
    const int nblk = blockIdx.x * 128, b = blockIdx.y, z = blockIdx.z;
    const int wn = wid >> 1, wd = wid & 1;

    float c[2][4][4];
#pragma unroll
    for (int i = 0; i < 2; i++)
#pragma unroll
        for (int j = 0; j < 4; j++)
#pragma unroll
            for (int r = 0; r < 4; r++) c[i][j][r] = 0.f;

    const int ck0 = z * (NN / MSPLIT / 64);
    for (int ci = 0; ci < NN / MSPLIT / 64; ci++) {
        const int m0c = (ck0 + ci) * 64;
        __syncthreads();
        if (t < 64) {
            scm[t] = g_cmax[b * NN + m0c + t];
            scr[t] = g_crcp[b * NN + m0c + t];
        }
        __syncthreads();

        // Stage P (128n x 64m): exp + hi/lo split, swizzled
        const float* sg = g_scores + ((size_t)b * NN + nblk) * NN + m0c;
#pragma unroll
        for (int i = 0; i < 8; i++) {
            int idx = i * 256 + t;
            int row = idx >> 4, c4 = idx & 15;
            float4 s4 = *(const float4*)(sg + (size_t)row * NN + c4 * 4);
            int ml = c4 * 4;
            float p0 = __expf(s4.x - scm[ml + 0]) * scr[ml + 0];
            float p1 = __expf(s4.y - scm[ml + 1]) * scr[ml + 1];
            float p2 = __expf(s4.z - scm[ml + 2]) * scr[ml + 2];
            float p3 = __expf(s4.w - scm[ml + 3]) * scr[ml + 3];
            uint32_t h01, l01, h23, l23;
            split2(p0, p1, h01, l01);
            split2(p2, p3, h23, l23);
            uint32_t off = (uint32_t)(row * 128 + (((c4 >> 1) ^ (row & 7)) << 4) +
                                      ((c4 & 1) << 3));
            *(uint2*)(smc + O_PH + off) = make_uint2(h01, h23);
            *(uint2*)(smc + O_PL + off) = make_uint2(l01, l23);
        }
        // Stage V (64m x 64d): hi/lo split, swizzled
        const float* vg = v + ((size_t)b * NN + m0c) * DD;
#pragma unroll
        for (int i = 0; i < 4; i++) {
            int idx = i * 256 + t;
            int row = idx >> 4, c4 = idx & 15;
            float4 v4 = *(const float4*)(vg + (size_t)row * DD + c4 * 4);
            uint32_t h01, l01, h23, l23;
            split2(v4.x, v4.y, h01, l01);
            split2(v4.z, v4.w, h23, l23);
            uint32_t off = (uint32_t)(row * 128 + (((c4 >> 1) ^ (row & 7)) << 4) +
                                      ((c4 & 1) << 3));
            *(uint2*)(smc + O_VH + off) = make_uint2(h01, h23);
            *(uint2*)(smc + O_VL + off) = make_uint2(l01, l23);
        }
        __syncthreads();

#pragma unroll
        for (int pass = 0; pass < 3; pass++) {
            const uint32_t Ab = sb + ((pass == 2) ? O_PL : O_PH);
            const uint32_t Bb = sb + ((pass == 1) ? O_VL : O_VH);
#pragma unroll
            for (int ks = 0; ks < 4; ks++) {
                uint32_t a[2][4], bf[2][4];
#pragma unroll
                for (int fn = 0; fn < 2; fn++) {
                    int row = wn * 32 + fn * 16 + (l & 15);
                    int blk = ks * 2 + (l >> 4);
                    LDSM4(a[fn], Ab + row * 128 + ((blk ^ (row & 7)) << 4));
                }
#pragma unroll
                for (int p = 0; p < 2; p++) {
                    int row = ks * 16 + ((l >> 3) & 1) * 8 + (l & 7);
                    int blk = wd * 4 + p * 2 + (l >> 4);
                    LDSM4T(bf[p], Bb + row * 128 + ((blk ^ (row & 7)) << 4));
                }
#pragma unroll
                for (int fn = 0; fn < 2; fn++)
#pragma unroll
                    for (int fb = 0; fb < 4; fb++)
                        MMA_BF16(c[fn][fb], a[fn], &bf[fb >> 1][(fb & 1) * 2]);
            }
        }
    }

    float* po = g_pout + (size_t)z * BB * NN * DD;
    const int g = l >> 2, tig = l & 3;
#pragma unroll
    for (int fn = 0; fn < 2; fn++) {
#pragma unroll
        for (int h = 0; h < 2; h++) {
            int n = nblk + wn * 32 + fn * 16 + g + h * 8;
#pragma unroll
            for (int fb = 0; fb < 4; fb++) {
                int d = wd * 32 + fb * 8 + tig * 2;
                float2 o = make_float2(c[fn][fb][h * 2], c[fn][fb][h * 2 + 1]);
                *(float2*)(po + ((size_t)b * NN + n) * DD + d) = o;
            }
        }
    }
}

// ============================================================================
// Kernel 4: reduce MSPLIT partials -> out (deterministic order)
// ============================================================================
__global__ void reduce_kernel(float* __restrict__ out) {
    size_t i = (size_t)blockIdx.x * 256 + threadIdx.x;   // float4 index
    const size_t stride = (size_t)BB * NN * DD / 4;
    float4 a = ((const float4*)g_pout)[i];
#pragma unroll
    for (int z = 1; z < MSPLIT; z++) {
        float4 p = ((const float4*)g_pout)[z * stride + i];
        a.x += p.x; a.y += p.y; a.z += p.z; a.w += p.w;
    }
    ((float4*)out)[i] = a;
}

// ============================================================================
extern "C" void kernel_launch(void* const* d_in, const int* in_sizes, int n_in,
                              void* d_out, int out_size) {
    const float* q = (const float*)d_in[0];
    const float* k = (const float*)d_in[1];
    const float* v = (const float*)d_in[2];
    const int* mask = (const int*)d_in[3];
    float* out = (float*)d_out;

    cudaFuncSetAttribute(scores_mma_kernel,
                         cudaFuncAttributeMaxDynamicSharedMemorySize, SC_SMEM);
    cudaFuncSetAttribute(out_mma_kernel,
                         cudaFuncAttributeMaxDynamicSharedMemorySize, O_SMEM);

    prep_kernel<<<2048, 256>>>(q, k);
    scores_mma_kernel<<<dim3(NN / 128, NN / 128, BB), 256, SC_SMEM>>>(mask);
    colstats1_kernel<<<dim3(NN / 256, NCHUNK, BB), 256>>>();
    colstats2_kernel<<<dim3(NN / 256, BB), 256>>>();
    out_mma_kernel<<<dim3(NN / 128, BB, MSPLIT), 256, O_SMEM>>>(v);
    reduce_kernel<<<BB * NN * DD / 4 / 256, 256>>>(out);
}

// round 8
// speedup vs baseline: 2.9371x; 1.0541x over previous
#include <cuda_runtime.h>
#include <cuda_bf16.h>
#include <cuda_fp16.h>
#include <cstdint>
#include <cstddef>

#define BB 16
#define NN 2048
#define DD 64
#define SCALE 0.022097086912079608f   // 1/sqrt(2048)
#define NEG_FILL -1000.0f
#define MSPLIT 4
#define NCHUNK 16

// ---------------------------------------------------------------------------
// Scratch (no allocations allowed)
// ---------------------------------------------------------------------------
__device__ __half g_scores[(size_t)BB * NN * NN];  // [b][n][m], m contiguous
__device__ float g_cmax[BB * NN];
__device__ float g_crcp[BB * NN];
__device__ float g_pmx[NCHUNK * BB * NN];
__device__ float g_psum[NCHUNK * BB * NN];
__device__ float g_pout[(size_t)MSPLIT * BB * NN * DD];
__device__ __align__(16) __nv_bfloat16 g_qh[(size_t)BB * NN * DD];
__device__ __align__(16) __nv_bfloat16 g_ql[(size_t)BB * NN * DD];
__device__ __align__(16) __nv_bfloat16 g_kh[(size_t)BB * NN * DD];
__device__ __align__(16) __nv_bfloat16 g_kl[(size_t)BB * NN * DD];

// ---------------------------------------------------------------------------
// Helpers
// ---------------------------------------------------------------------------
__device__ __forceinline__ uint32_t smem_u32(const void* p) {
    uint32_t a;
    asm("{ .reg .u64 t; cvta.to.shared.u64 t, %1; cvt.u32.u64 %0, t; }"
        : "=r"(a) : "l"(p));
    return a;
}

#define LDSM4(r, a)                                                            \
    asm volatile("ldmatrix.sync.aligned.m8n8.x4.shared.b16 {%0,%1,%2,%3}, [%4];" \
        : "=r"((r)[0]), "=r"((r)[1]), "=r"((r)[2]), "=r"((r)[3]) : "r"(a))
#define LDSM4T(r, a)                                                           \
    asm volatile("ldmatrix.sync.aligned.m8n8.x4.trans.shared.b16 {%0,%1,%2,%3}, [%4];" \
        : "=r"((r)[0]), "=r"((r)[1]), "=r"((r)[2]), "=r"((r)[3]) : "r"(a))
#define MMA_BF16(c, a, b)                                                      \
    asm volatile("mma.sync.aligned.m16n8k16.row.col.f32.bf16.bf16.f32 "        \
        "{%0,%1,%2,%3}, {%4,%5,%6,%7}, {%8,%9}, {%0,%1,%2,%3};"                \
        : "+f"((c)[0]), "+f"((c)[1]), "+f"((c)[2]), "+f"((c)[3])               \
        : "r"((a)[0]), "r"((a)[1]), "r"((a)[2]), "r"((a)[3]),                  \
          "r"((b)[0]), "r"((b)[1]))

__device__ __forceinline__ void split2(float x, float y, uint32_t& hi, uint32_t& lo) {
    __nv_bfloat16 hx = __float2bfloat16(x), hy = __float2bfloat16(y);
    __nv_bfloat16 lx = __float2bfloat16(x - __bfloat162float(hx));
    __nv_bfloat16 ly = __float2bfloat16(y - __bfloat162float(hy));
    hi = (uint32_t)__bfloat16_as_ushort(hx) | ((uint32_t)__bfloat16_as_ushort(hy) << 16);
    lo = (uint32_t)__bfloat16_as_ushort(lx) | ((uint32_t)__bfloat16_as_ushort(ly) << 16);
}

// ============================================================================
// Kernel 0: split q, k into bf16 hi/lo
// ============================================================================
__global__ void prep_kernel(const float* __restrict__ q,
                            const float* __restrict__ k) {
    int i = blockIdx.x * 256 + threadIdx.x;     // float4 index, 524288 total
    float4 vq = ((const float4*)q)[i];
    float4 vk = ((const float4*)k)[i];
    uint32_t h0, h1, l0, l1;
    split2(vq.x, vq.y, h0, l0); split2(vq.z, vq.w, h1, l1);
    ((uint2*)g_qh)[i] = make_uint2(h0, h1);
    ((uint2*)g_ql)[i] = make_uint2(l0, l1);
    split2(vk.x, vk.y, h0, l0); split2(vk.z, vk.w, h1, l1);
    ((uint2*)g_kh)[i] = make_uint2(h0, h1);
    ((uint2*)g_kl)[i] = make_uint2(l0, l1);
}

// ============================================================================
// Kernel 1: scores via HMMA + fused per-column partial softmax stats.
// Block 128(n) x 128(m); 8 warps in 2(n) x 4(m); warp tile 64x32.
// Stores fp16 scores; writes per-(b, n-block) column stats partials.
// ============================================================================
#define SC_SMEM 65536

__global__ void __launch_bounds__(256, 2)
scores_mma_kernel(const int* __restrict__ mask) {
    extern __shared__ char smc[];
    const uint32_t sb = smem_u32(smc);
    const int t = threadIdx.x, l = t & 31, wid = t >> 5;
    const int m0 = blockIdx.x * 128, n0 = blockIdx.y * 128, b = blockIdx.z;
    const int nb = blockIdx.y;
    const int wn = wid >> 2, wm = wid & 3;

    const uint32_t QH = 0, QL = 16384, KH = 32768, KL = 49152;

    {
        const uint4* qh = (const uint4*)(g_qh + ((size_t)b * NN + n0) * DD);
        const uint4* ql = (const uint4*)(g_ql + ((size_t)b * NN + n0) * DD);
        const uint4* kh = (const uint4*)(g_kh + ((size_t)b * NN + m0) * DD);
        const uint4* kl = (const uint4*)(g_kl + ((size_t)b * NN + m0) * DD);
#pragma unroll
        for (int i = 0; i < 4; i++) {
            int idx = i * 256 + t;
            int row = idx >> 3, q = idx & 7;
            uint32_t off = (uint32_t)(row * 128 + ((q ^ (row & 7)) << 4));
            *(uint4*)(smc + QH + off) = qh[idx];
            *(uint4*)(smc + QL + off) = ql[idx];
            *(uint4*)(smc + KH + off) = kh[idx];
            *(uint4*)(smc + KL + off) = kl[idx];
        }
    }
    __syncthreads();

    float c[4][4][4];
#pragma unroll
    for (int i = 0; i < 4; i++)
#pragma unroll
        for (int j = 0; j < 4; j++)
#pragma unroll
            for (int r = 0; r < 4; r++) c[i][j][r] = 0.f;

#pragma unroll
    for (int pass = 0; pass < 3; pass++) {
        const uint32_t Ab = sb + ((pass == 2) ? QL : QH);
        const uint32_t Bb = sb + ((pass == 1) ? KL : KH);
#pragma unroll
        for (int ks = 0; ks < 4; ks++) {
            uint32_t a[4][4], bf[2][4];
#pragma unroll
            for (int fn = 0; fn < 4; fn++) {
                int row = wn * 64 + fn * 16 + (l & 15);
                int blk = ks * 2 + (l >> 4);
                LDSM4(a[fn], Ab + row * 128 + ((blk ^ (row & 7)) << 4));
            }
#pragma unroll
            for (int p = 0; p < 2; p++) {
                int row = wm * 32 + p * 16 + ((l >> 4) << 3) + (l & 7);
                int blk = ks * 2 + ((l >> 3) & 1);
                LDSM4(bf[p], Bb + row * 128 + ((blk ^ (row & 7)) << 4));
            }
#pragma unroll
            for (int fn = 0; fn < 4; fn++)
#pragma unroll
                for (int fm = 0; fm < 4; fm++)
                    MMA_BF16(c[fn][fm], a[fn], &bf[fm >> 1][(fm & 1) * 2]);
        }
    }

    // Epilogue: scale + mask + round to fp16 + store; keep rounded values in c
    const int g = l >> 2, tig = l & 3;
#pragma unroll
    for (int fn = 0; fn < 4; fn++) {
#pragma unroll
        for (int h = 0; h < 2; h++) {
            int n = n0 + wn * 64 + fn * 16 + g + h * 8;
#pragma unroll
            for (int fm = 0; fm < 4; fm++) {
                int m = m0 + wm * 32 + fm * 8 + tig * 2;
                size_t addr = ((size_t)b * NN + n) * NN + m;
                int2 mk = *(const int2*)(mask + addr);
                float x = mk.x ? NEG_FILL : c[fn][fm][h * 2] * SCALE;
                float y = mk.y ? NEG_FILL : c[fn][fm][h * 2 + 1] * SCALE;
                __half2 hh = __floats2half2_rn(x, y);
                *(__half2*)(g_scores + addr) = hh;
                c[fn][fm][h * 2]     = __half2float(__low2half(hh));
                c[fn][fm][h * 2 + 1] = __half2float(__high2half(hh));
            }
        }
    }

    // Per-thread column stats: 8 columns (fm x e), 8 rows each (fn x h)
    float cm[4][2], cs[4][2];
#pragma unroll
    for (int fm = 0; fm < 4; fm++) {
        cm[fm][0] = -3.4e38f; cm[fm][1] = -3.4e38f;
        cs[fm][0] = 0.f;      cs[fm][1] = 0.f;
    }
#pragma unroll
    for (int fn = 0; fn < 4; fn++)
#pragma unroll
        for (int h = 0; h < 2; h++)
#pragma unroll
            for (int fm = 0; fm < 4; fm++) {
                cm[fm][0] = fmaxf(cm[fm][0], c[fn][fm][h * 2]);
                cm[fm][1] = fmaxf(cm[fm][1], c[fn][fm][h * 2 + 1]);
            }
#pragma unroll
    for (int fn = 0; fn < 4; fn++)
#pragma unroll
        for (int h = 0; h < 2; h++)
#pragma unroll
            for (int fm = 0; fm < 4; fm++) {
                cs[fm][0] += __expf(c[fn][fm][h * 2] - cm[fm][0]);
                cs[fm][1] += __expf(c[fn][fm][h * 2 + 1] - cm[fm][1]);
            }
    // Butterfly over g lanes (stride 4, 8, 16)
#pragma unroll
    for (int st = 4; st <= 16; st <<= 1) {
#pragma unroll
        for (int fm = 0; fm < 4; fm++)
#pragma unroll
            for (int e = 0; e < 2; e++) {
                float om = __shfl_xor_sync(0xFFFFFFFFu, cm[fm][e], st);
                float os = __shfl_xor_sync(0xFFFFFFFFu, cs[fm][e], st);
                float nm = fmaxf(cm[fm][e], om);
                cs[fm][e] = cs[fm][e] * __expf(cm[fm][e] - nm) +
                            os * __expf(om - nm);
                cm[fm][e] = nm;
            }
    }
    // Combine the two n-warps via smem (reuse tile region)
    __syncthreads();
    float* smx = (float*)smc;          // [2][128]
    float* sms = smx + 256;
    if (l < 4) {
#pragma unroll
        for (int fm = 0; fm < 4; fm++)
#pragma unroll
            for (int e = 0; e < 2; e++) {
                int ml = wm * 32 + fm * 8 + l * 2 + e;
                smx[wn * 128 + ml] = cm[fm][e];
                sms[wn * 128 + ml] = cs[fm][e];
            }
    }
    __syncthreads();
    if (t < 128) {
        float m1 = smx[t], m2 = smx[128 + t];
        float s1 = sms[t], s2 = sms[128 + t];
        float nm = fmaxf(m1, m2);
        float S = s1 * __expf(m1 - nm) + s2 * __expf(m2 - nm);
        g_pmx[(nb * BB + b) * NN + m0 + t] = nm;
        g_psum[(nb * BB + b) * NN + m0 + t] = S;
    }
}

// ============================================================================
// Kernel 2: combine NCHUNK partials -> g_cmax, g_crcp
// ============================================================================
__global__ void colstats2_kernel() {
    const int m = blockIdx.x * 256 + threadIdx.x;
    const int b = blockIdx.y;
    float mx = -3.4e38f;
    float lm[NCHUNK], ls[NCHUNK];
#pragma unroll
    for (int i = 0; i < NCHUNK; i++) {
        lm[i] = g_pmx[(i * BB + b) * NN + m];
        ls[i] = g_psum[(i * BB + b) * NN + m];
        mx = fmaxf(mx, lm[i]);
    }
    float S = 0.f;
#pragma unroll
    for (int i = 0; i < NCHUNK; i++) S += ls[i] * __expf(lm[i] - mx);
    g_cmax[b * NN + m] = mx;
    g_crcp[b * NN + m] = 1.f / S;
}

// ============================================================================
// Kernel 3: partial out = P·V via HMMA over an m-range of NN/MSPLIT.
// Block 128(n) x 64(d); k-chunks of 64 m. grid (NN/128, BB, MSPLIT).
// P read as fp16, exp+split during staging.
// ============================================================================
#define O_PH 0
#define O_PL 16384
#define O_VH 32768
#define O_VL 40960
#define O_CM 49152
#define O_CR 49408
#define O_SMEM 49664

__global__ void __launch_bounds__(256, 2)
out_mma_kernel(const float* __restrict__ v) {
    extern __shared__ char smc[];
    const uint32_t sb = smem_u32(smc);
    float* scm = (float*)(smc + O_CM);
    float* scr = (float*)(smc + O_CR);
    const int t = threadIdx.x, l = t & 31, wid = t >> 5;
    const int nblk = blockIdx.x * 128, b = blockIdx.y, z = blockIdx.z;
    const int wn = wid >> 1, wd = wid & 1;

    float c[2][4][4];
#pragma unroll
    for (int i = 0; i < 2; i++)
#pragma unroll
        for (int j = 0; j < 4; j++)
#pragma unroll
            for (int r = 0; r < 4; r++) c[i][j][r] = 0.f;

    const int ck0 = z * (NN / MSPLIT / 64);
    for (int ci = 0; ci < NN / MSPLIT / 64; ci++) {
        const int m0c = (ck0 + ci) * 64;
        __syncthreads();
        if (t < 64) {
            scm[t] = g_cmax[b * NN + m0c + t];
            scr[t] = g_crcp[b * NN + m0c + t];
        }
        __syncthreads();

        // Stage P (128n x 64m): fp16 load, exp + hi/lo split, swizzled
        const __half* sg = g_scores + ((size_t)b * NN + nblk) * NN + m0c;
#pragma unroll
        for (int i = 0; i < 4; i++) {
            int idx = i * 256 + t;
            int row = idx >> 3, c8 = idx & 7;
            uint4 raw = *(const uint4*)(sg + (size_t)row * NN + c8 * 8);
            const __half2* hp = (const __half2*)&raw;
            int ml = c8 * 8;
            uint32_t hv[4], lv[4];
#pragma unroll
            for (int p = 0; p < 4; p++) {
                float2 sf = __half22float2(hp[p]);
                float p0 = __expf(sf.x - scm[ml + 2 * p]) * scr[ml + 2 * p];
                float p1 = __expf(sf.y - scm[ml + 2 * p + 1]) * scr[ml + 2 * p + 1];
                split2(p0, p1, hv[p], lv[p]);
            }
            uint32_t off = (uint32_t)(row * 128 + ((c8 ^ (row & 7)) << 4));
            *(uint4*)(smc + O_PH + off) = make_uint4(hv[0], hv[1], hv[2], hv[3]);
            *(uint4*)(smc + O_PL + off) = make_uint4(lv[0], lv[1], lv[2], lv[3]);
        }
        // Stage V (64m x 64d): hi/lo split, swizzled
        const float* vg = v + ((size_t)b * NN + m0c) * DD;
#pragma unroll
        for (int i = 0; i < 4; i++) {
            int idx = i * 256 + t;
            int row = idx >> 4, c4 = idx & 15;
            float4 v4 = *(const float4*)(vg + (size_t)row * DD + c4 * 4);
            uint32_t h01, l01, h23, l23;
            split2(v4.x, v4.y, h01, l01);
            split2(v4.z, v4.w, h23, l23);
            uint32_t off = (uint32_t)(row * 128 + (((c4 >> 1) ^ (row & 7)) << 4) +
                                      ((c4 & 1) << 3));
            *(uint2*)(smc + O_VH + off) = make_uint2(h01, h23);
            *(uint2*)(smc + O_VL + off) = make_uint2(l01, l23);
        }
        __syncthreads();

#pragma unroll
        for (int pass = 0; pass < 3; pass++) {
            const uint32_t Ab = sb + ((pass == 2) ? O_PL : O_PH);
            const uint32_t Bb = sb + ((pass == 1) ? O_VL : O_VH);
#pragma unroll
            for (int ks = 0; ks < 4; ks++) {
                uint32_t a[2][4], bf[2][4];
#pragma unroll
                for (int fn = 0; fn < 2; fn++) {
                    int row = wn * 32 + fn * 16 + (l & 15);
                    int blk = ks * 2 + (l >> 4);
                    LDSM4(a[fn], Ab + row * 128 + ((blk ^ (row & 7)) << 4));
                }
#pragma unroll
                for (int p = 0; p < 2; p++) {
                    int row = ks * 16 + ((l >> 3) & 1) * 8 + (l & 7);
                    int blk = wd * 4 + p * 2 + (l >> 4);
                    LDSM4T(bf[p], Bb + row * 128 + ((blk ^ (row & 7)) << 4));
                }
#pragma unroll
                for (int fn = 0; fn < 2; fn++)
#pragma unroll
                    for (int fb = 0; fb < 4; fb++)
                        MMA_BF16(c[fn][fb], a[fn], &bf[fb >> 1][(fb & 1) * 2]);
            }
        }
    }

    float* po = g_pout + (size_t)z * BB * NN * DD;
    const int g = l >> 2, tig = l & 3;
#pragma unroll
    for (int fn = 0; fn < 2; fn++) {
#pragma unroll
        for (int h = 0; h < 2; h++) {
            int n = nblk + wn * 32 + fn * 16 + g + h * 8;
#pragma unroll
            for (int fb = 0; fb < 4; fb++) {
                int d = wd * 32 + fb * 8 + tig * 2;
                float2 o = make_float2(c[fn][fb][h * 2], c[fn][fb][h * 2 + 1]);
                *(float2*)(po + ((size_t)b * NN + n) * DD + d) = o;
            }
        }
    }
}

// ============================================================================
// Kernel 4: reduce MSPLIT partials -> out (deterministic order)
// ============================================================================
__global__ void reduce_kernel(float* __restrict__ out) {
    size_t i = (size_t)blockIdx.x * 256 + threadIdx.x;   // float4 index
    const size_t stride = (size_t)BB * NN * DD / 4;
    float4 a = ((const float4*)g_pout)[i];
#pragma unroll
    for (int z = 1; z < MSPLIT; z++) {
        float4 p = ((const float4*)g_pout)[z * stride + i];
        a.x += p.x; a.y += p.y; a.z += p.z; a.w += p.w;
    }
    ((float4*)out)[i] = a;
}

// ============================================================================
extern "C" void kernel_launch(void* const* d_in, const int* in_sizes, int n_in,
                              void* d_out, int out_size) {
    const float* q = (const float*)d_in[0];
    const float* k = (const float*)d_in[1];
    const float* v = (const float*)d_in[2];
    const int* mask = (const int*)d_in[3];
    float* out = (float*)d_out;

    cudaFuncSetAttribute(scores_mma_kernel,
                         cudaFuncAttributeMaxDynamicSharedMemorySize, SC_SMEM);
    cudaFuncSetAttribute(out_mma_kernel,
                         cudaFuncAttributeMaxDynamicSharedMemorySize, O_SMEM);

    prep_kernel<<<2048, 256>>>(q, k);
    scores_mma_kernel<<<dim3(NN / 128, NN / 128, BB), 256, SC_SMEM>>>(mask);
    colstats2_kernel<<<dim3(NN / 256, BB), 256>>>();
    out_mma_kernel<<<dim3(NN / 128, BB, MSPLIT), 256, O_SMEM>>>(v);
    reduce_kernel<<<BB * NN * DD / 4 / 256, 256>>>(out);
}